// round 3
// baseline (speedup 1.0000x reference)
#include <cuda_runtime.h>
#include <math.h>

#define NE   100000
#define NR   200
#define EE   500000
#define IND  128
#define OUTD 200
#define K3   456   // 128 (ent_s) + 128 (P3/obj) + 200 (A row)

// ---------------- scratch (__device__ globals; no allocations) ----------------
__device__ float g_ent_rn[NE * IND];       // renormed entity table (51.2 MB)
__device__ float g_rel_rn[NR * IND];
__device__ float g_d1[NE];
__device__ float g_d3[NE];
__device__ float g_d2[NR];
__device__ float g_weff[385];              // [0..383] w_eff, [384] bias_eff
__device__ float g_A[NE * NR];             // e_b accumulated by (s, r)  (80 MB)
__device__ float g_P3[NE * IND];           // sum e_b * ent_rn[o] by s   (51.2 MB)
__device__ float g_ebs[NE];
__device__ float g_inv[NE];
__device__ float g_Wfull[K3 * OUTD];       // [WaL; WaR; M1] stacked, row-major KxJ
__device__ float g_eb[EE];
__device__ int   g_hist[NR];
__device__ int   g_offs[NR];
__device__ int   g_cur[NR];
__device__ int   g_sS[EE];
__device__ int   g_sO[EE];
__device__ int   g_sR[EE];
__device__ float g_sE[EE];
__device__ float g_S1[NR * IND];           // sum e_b*ent_rn[s] by r
__device__ float g_S2[NR * IND];           // sum e_b*ent_rn[o] by r
__device__ float g_ebr[NR];

// ---------------- zero scratch ----------------
__global__ void kz() {
    long i  = (long)blockIdx.x * blockDim.x + threadIdx.x;
    long stride = (long)gridDim.x * blockDim.x;
    const long nA4 = (long)NE * NR / 4;
    const long nP4 = (long)NE * IND / 4;
    float4 z = make_float4(0.f, 0.f, 0.f, 0.f);
    for (long t = i; t < nA4 + nP4; t += stride) {
        if (t < nA4) ((float4*)g_A)[t] = z;
        else         ((float4*)g_P3)[t - nA4] = z;
    }
    if (i < NE) { g_ebs[i] = 0.f; }
    if (i < NR * IND) { g_S1[i] = 0.f; g_S2[i] = 0.f; }
    if (i < NR) { g_hist[i] = 0; g_ebr[i] = 0.f; }
}

// ---------------- w_eff = Wa2 @ Wa ; bias_eff = Wa2.ba + ba2 ----------------
__global__ void kw(const float* __restrict__ Wa, const float* __restrict__ ba,
                   const float* __restrict__ Wa2, const float* __restrict__ ba2) {
    int k = threadIdx.x;
    if (k < 384) {
        float acc = 0.f;
        for (int j = 0; j < OUTD; j++) acc += Wa2[j] * Wa[j * 384 + k];
        g_weff[k] = acc;
    } else if (k == 384) {
        float acc = ba2[0];
        for (int j = 0; j < OUTD; j++) acc += Wa2[j] * ba[j];
        g_weff[384] = acc;
    }
}

// ---------------- renorm rows + per-row dots (warp per row) ----------------
__device__ __forceinline__ float warp_sum(float v) {
    #pragma unroll
    for (int off = 16; off >= 1; off >>= 1) v += __shfl_xor_sync(0xffffffffu, v, off);
    return v;
}

__global__ void krn_ent(const float* __restrict__ ent) {
    int w    = ((int)blockIdx.x * blockDim.x + threadIdx.x) >> 5;
    int lane = threadIdx.x & 31;
    if (w >= NE) return;
    float4 v = *(const float4*)&ent[(long)w * IND + lane * 4];
    float ss = warp_sum(v.x * v.x + v.y * v.y + v.z * v.z + v.w * v.w);
    float nrm = sqrtf(ss);
    float sc  = fminf(1.f, 1.f / fmaxf(nrm, 1e-12f));
    float4 r = make_float4(v.x * sc, v.y * sc, v.z * sc, v.w * sc);
    *(float4*)&g_ent_rn[(long)w * IND + lane * 4] = r;
    float4 w1 = *(const float4*)&g_weff[lane * 4];
    float4 w3 = *(const float4*)&g_weff[256 + lane * 4];
    float a1 = warp_sum(r.x * w1.x + r.y * w1.y + r.z * w1.z + r.w * w1.w);
    float a3 = warp_sum(r.x * w3.x + r.y * w3.y + r.z * w3.z + r.w * w3.w);
    if (lane == 0) { g_d1[w] = a1; g_d3[w] = a3; }
}

__global__ void krn_rel(const float* __restrict__ rel) {
    int w    = ((int)blockIdx.x * blockDim.x + threadIdx.x) >> 5;
    int lane = threadIdx.x & 31;
    if (w >= NR) return;
    float4 v = *(const float4*)&rel[(long)w * IND + lane * 4];
    float ss = warp_sum(v.x * v.x + v.y * v.y + v.z * v.z + v.w * v.w);
    float nrm = sqrtf(ss);
    float sc  = fminf(1.f, 1.f / fmaxf(nrm, 1e-12f));
    float4 r = make_float4(v.x * sc, v.y * sc, v.z * sc, v.w * sc);
    *(float4*)&g_rel_rn[(long)w * IND + lane * 4] = r;
    float4 w2 = *(const float4*)&g_weff[128 + lane * 4];
    float a2 = warp_sum(r.x * w2.x + r.y * w2.y + r.z * w2.z + r.w * w2.w);
    if (lane == 0) g_d2[w] = a2;
}

// ---------------- build Wfull = [WaL(128); WaR(128); M1(200)] ----------------
__global__ void kwf(const float* __restrict__ Wa) {
    int idx = (int)blockIdx.x * blockDim.x + threadIdx.x;
    if (idx >= K3 * OUTD) return;
    int k = idx / OUTD, j = idx % OUTD;
    float v;
    if (k < 128) {
        v = Wa[j * 384 + k];                       // WaL (pairs with ent_rn[s])
    } else if (k < 256) {
        v = Wa[j * 384 + 256 + (k - 128)];         // WaR (pairs with P3 = obj sums)
    } else {
        int r = k - 256;                           // M1[r][j] = rel_rn[r] . Wa_mid[j]
        float acc = 0.f;
        const float* rr = &g_rel_rn[r * IND];
        const float* wm = &Wa[j * 384 + 128];
        #pragma unroll 4
        for (int c = 0; c < IND; c++) acc += rr[c] * wm[c];
        v = acc;
    }
    g_Wfull[k * OUTD + j] = v;
}

// ---------------- edge pass (warp per edge): e_b, A, ebs, hist, P3 ----------------
__global__ void kc(const int* __restrict__ trip) {
    int gw   = ((int)blockIdx.x * blockDim.x + threadIdx.x) >> 5;
    int lane = threadIdx.x & 31;
    if (gw >= EE) return;
    int s = trip[3 * gw], r = trip[3 * gw + 1], o = trip[3 * gw + 2];
    float x  = g_d1[s] + g_d2[r] + g_d3[o] + g_weff[384];
    float lr = x >= 0.f ? x : 0.01f * x;   // leaky_relu slope 0.01
    float e  = expf(-lr);
    if (lane == 0) {
        g_eb[gw] = e;
        atomicAdd(&g_A[(long)s * NR + r], e);
        atomicAdd(&g_ebs[s], e);
        atomicAdd(&g_hist[r], 1);
    }
    float4 v = *(const float4*)&g_ent_rn[(long)o * IND + lane * 4];
    float* p = &g_P3[(long)s * IND + lane * 4];
    atomicAdd(p + 0, e * v.x);
    atomicAdd(p + 1, e * v.y);
    atomicAdd(p + 2, e * v.z);
    atomicAdd(p + 3, e * v.w);
}

// ---------------- exclusive scan of hist (R=200, trivial) ----------------
__global__ void kscan() {
    if (threadIdx.x == 0 && blockIdx.x == 0) {
        int acc = 0;
        for (int r = 0; r < NR; r++) {
            g_offs[r] = acc; g_cur[r] = acc; acc += g_hist[r];
        }
    }
}

// ---------------- scatter edges sorted by relation ----------------
__global__ void kscatter(const int* __restrict__ trip) {
    int e = (int)blockIdx.x * blockDim.x + threadIdx.x;
    if (e >= EE) return;
    int r = trip[3 * e + 1];
    int pos = atomicAdd(&g_cur[r], 1);
    g_sS[pos] = trip[3 * e];
    g_sO[pos] = trip[3 * e + 2];
    g_sR[pos] = r;
    g_sE[pos] = g_eb[e];
}

// ---------------- relation-side sums over sorted chunks ----------------
#define RCH 256
__global__ void kr() {
    int st = (int)blockIdx.x * RCH;
    if (st >= EE) return;
    int en = st + RCH; if (en > EE) en = EE;
    int t = threadIdx.x;                 // 256 threads: t<128 -> S1, else S2
    int d = t & 127;
    bool lo = t < 128;
    float acc = 0.f, ebsum = 0.f;
    int curr = g_sR[st];
    #pragma unroll 4
    for (int i = st; i < en; i++) {
        int rr = g_sR[i];
        if (rr != curr) {
            atomicAdd(lo ? &g_S1[curr * IND + d] : &g_S2[curr * IND + d], acc);
            if (t == 0) atomicAdd(&g_ebr[curr], ebsum);
            acc = 0.f; ebsum = 0.f; curr = rr;
        }
        float e = g_sE[i];
        int node = lo ? g_sS[i] : g_sO[i];
        acc += e * g_ent_rn[(long)node * IND + d];
        ebsum += e;
    }
    atomicAdd(lo ? &g_S1[curr * IND + d] : &g_S2[curr * IND + d], acc);
    if (t == 0) atomicAdd(&g_ebr[curr], ebsum);
}

// ---------------- inverse ebs ----------------
__global__ void kebs() {
    int n = (int)blockIdx.x * blockDim.x + threadIdx.x;
    if (n >= NE) return;
    float e = g_ebs[n];
    g_inv[n] = (e > 0.f) ? 1.f / e : 0.f;
}

// ---------------- main fused GEMM: out_ent = relu(mask*(X@W + ba)) ----------------
// X[n] = [ent_rn[n](128) | P3[n](128) | A[n,:](200)], parts 2,3 scaled by inv_ebs
#define BM 64
#define BN 64
#define KT 16
__global__ void __launch_bounds__(256) kg(const float* __restrict__ ba,
                                          float* __restrict__ out) {
    __shared__ float Xs[KT][BM + 4];
    __shared__ float Ws[KT][BN];
    int n0 = (int)blockIdx.x * BM;
    int j0 = (int)blockIdx.y * BN;
    int tid = threadIdx.x;
    int tx = tid & 15, ty = tid >> 4;
    float accA[4][4] = {}, accB[4][4] = {};
    const int nchunks = (K3 + KT - 1) / KT;  // 29
    for (int c = 0; c < nchunks; c++) {
        int k0 = c * KT;
        #pragma unroll
        for (int it = 0; it < 4; it++) {
            int idx = tid + it * 256;
            int kk = idx & 15, i = idx >> 4;
            int n = n0 + i, k = k0 + kk;
            float v = 0.f;
            if (n < NE && k < K3) {
                if (k < 128)      v = g_ent_rn[(long)n * IND + k];
                else if (k < 256) v = g_P3[(long)n * IND + (k - 128)];
                else              v = g_A[(long)n * NR + (k - 256)];
            }
            Xs[kk][i] = v;
        }
        #pragma unroll
        for (int it = 0; it < 4; it++) {
            int idx = tid + it * 256;
            int j = idx & 63, kk = idx >> 6;
            int jj = j0 + j, k = k0 + kk;
            Ws[kk][j] = (jj < OUTD && k < K3) ? g_Wfull[k * OUTD + jj] : 0.f;
        }
        __syncthreads();
        if (k0 < 128) {  // chunks 0..7 belong to the unscaled ent part
            #pragma unroll
            for (int kk = 0; kk < KT; kk++) {
                float4 a = *(float4*)&Xs[kk][ty * 4];
                float4 b = *(float4*)&Ws[kk][tx * 4];
                float av[4] = {a.x, a.y, a.z, a.w};
                float bv[4] = {b.x, b.y, b.z, b.w};
                #pragma unroll
                for (int ii = 0; ii < 4; ii++)
                    #pragma unroll
                    for (int jj = 0; jj < 4; jj++)
                        accA[ii][jj] += av[ii] * bv[jj];
            }
        } else {
            #pragma unroll
            for (int kk = 0; kk < KT; kk++) {
                float4 a = *(float4*)&Xs[kk][ty * 4];
                float4 b = *(float4*)&Ws[kk][tx * 4];
                float av[4] = {a.x, a.y, a.z, a.w};
                float bv[4] = {b.x, b.y, b.z, b.w};
                #pragma unroll
                for (int ii = 0; ii < 4; ii++)
                    #pragma unroll
                    for (int jj = 0; jj < 4; jj++)
                        accB[ii][jj] += av[ii] * bv[jj];
            }
        }
        __syncthreads();
    }
    float bav[4];
    #pragma unroll
    for (int jj = 0; jj < 4; jj++) {
        int j = j0 + tx * 4 + jj;
        bav[jj] = (j < OUTD) ? ba[j] : 0.f;
    }
    #pragma unroll
    for (int ii = 0; ii < 4; ii++) {
        int n = n0 + ty * 4 + ii;
        if (n >= NE) continue;
        float inv = g_inv[n];
        #pragma unroll
        for (int jj = 0; jj < 4; jj++) {
            int j = j0 + tx * 4 + jj;
            if (j >= OUTD) continue;
            float v = (inv > 0.f)
                ? fmaxf(accA[ii][jj] + inv * accB[ii][jj] + bav[jj], 0.f)
                : 0.f;
            out[(long)n * OUTD + j] = v;
        }
    }
}

// ---------------- h_rel (tiny: 200x200) ----------------
__global__ void kh(const float* __restrict__ ba, float* __restrict__ out) {
    __shared__ float s1[IND], s2[IND];
    int r = blockIdx.x, j = threadIdx.x;   // 200 threads
    if (j < IND) { s1[j] = g_S1[r * IND + j]; s2[j] = g_S2[r * IND + j]; }
    __syncthreads();
    float ebr  = g_ebr[r];
    float icnt = 1.f / fmaxf((float)g_hist[r], 1.f);
    float acc = ebr * (g_Wfull[(256 + r) * OUTD + j] + ba[j]);
    #pragma unroll 4
    for (int c = 0; c < IND; c++) {
        acc += s1[c] * g_Wfull[c * OUTD + j];
        acc += s2[c] * g_Wfull[(128 + c) * OUTD + j];
    }
    out[(long)NE * OUTD + r * OUTD + j] = fmaxf(acc * icnt, 0.f);
}

// ---------------- launch ----------------
extern "C" void kernel_launch(void* const* d_in, const int* in_sizes, int n_in,
                              void* d_out, int out_size) {
    const int*   trip = (const int*)d_in[0];
    const float* ent  = (const float*)d_in[1];
    const float* rel  = (const float*)d_in[2];
    const float* Wa   = (const float*)d_in[3];
    const float* ba   = (const float*)d_in[4];
    const float* Wa2  = (const float*)d_in[5];
    const float* ba2  = (const float*)d_in[6];
    float* out = (float*)d_out;

    kz<<<4096, 256>>>();
    kw<<<1, 512>>>(Wa, ba, Wa2, ba2);
    krn_rel<<<(NR * 32 + 255) / 256, 256>>>(rel);
    krn_ent<<<(NE * 32 + 255) / 256, 256>>>(ent);
    kwf<<<(K3 * OUTD + 255) / 256, 256>>>(Wa);
    kc<<<(EE * 32 + 255) / 256, 256>>>(trip);
    kscan<<<1, 1>>>();
    kscatter<<<(EE + 255) / 256, 256>>>(trip);
    kr<<<(EE + RCH - 1) / RCH, 256>>>();
    kebs<<<(NE + 255) / 256, 256>>>();
    dim3 gg((NE + BM - 1) / BM, (OUTD + BN - 1) / BN);
    kg<<<gg, 256>>>(ba, out);
    kh<<<NR, OUTD>>>(ba, out);
}

// round 4
// speedup vs baseline: 2.5313x; 2.5313x over previous
#include <cuda_runtime.h>
#include <math.h>

#define NE   100000
#define NR   200
#define EE   500000
#define IND  128
#define OUTD 200
#define KK   384      // 128 ent_s | 128 P2(rel) | 128 P3(obj)

// ---------------- scratch ----------------
__device__ float g_ent_rn[NE * IND];
__device__ float g_rel_rn[NR * IND];
__device__ float g_P2[NE * IND];          // inv*sum e*rel_rn[r]  per subject
__device__ float g_P3[NE * IND];          // inv*sum e*ent_rn[o]  per subject
__device__ float g_inv[NE];
__device__ float g_d1[NE];
__device__ float g_d3[NE];
__device__ float g_d2[NR];
__device__ float g_weff[385];
__device__ float g_Wfull[KK * OUTD];      // Wa transposed: [k][j]
__device__ float g_eb[EE];
__device__ int   g_histS[NE];
__device__ int   g_offS[NE];
__device__ int   g_curS[NE];
__device__ int   g_histR[NR];
__device__ int   g_offR[NR];
__device__ int   g_curR[NR];
__device__ int   g_bsum[128];
__device__ int   g_boff[128];
__device__ unsigned int g_sRO[EE];        // edges sorted by s: (r<<17)|o
__device__ float g_sEb[EE];
__device__ int   g_rS[EE];                // edges sorted by r
__device__ int   g_rO[EE];
__device__ float g_rE[EE];
__device__ float g_S1[NR * IND];
__device__ float g_S2[NR * IND];
__device__ float g_ebr[NR];

// ---------------- f32x2 helpers ----------------
__device__ __forceinline__ void fma2(unsigned long long &d,
                                     unsigned long long a, unsigned long long b) {
    asm("fma.rn.f32x2 %0, %1, %2, %0;" : "+l"(d) : "l"(a), "l"(b));
}
__device__ __forceinline__ unsigned long long dup2(float x) {
    unsigned int u = __float_as_uint(x);
    unsigned long long r;
    asm("mov.b64 %0, {%1, %1};" : "=l"(r) : "r"(u));
    return r;
}
__device__ __forceinline__ void unpack2(unsigned long long v, float &lo, float &hi) {
    unsigned int a, b;
    asm("mov.b64 {%0, %1}, %2;" : "=r"(a), "=r"(b) : "l"(v));
    lo = __uint_as_float(a); hi = __uint_as_float(b);
}

// ---------------- zero small scratch ----------------
__global__ void kz() {
    int i = (int)blockIdx.x * blockDim.x + threadIdx.x;
    if (i < NE) g_histS[i] = 0;
    if (i < NR) { g_histR[i] = 0; g_ebr[i] = 0.f; }
    if (i < NR * IND) { g_S1[i] = 0.f; g_S2[i] = 0.f; }
}

// ---------------- w_eff = Wa2 @ Wa ; bias_eff ----------------
__global__ void kw(const float* __restrict__ Wa, const float* __restrict__ ba,
                   const float* __restrict__ Wa2, const float* __restrict__ ba2) {
    int k = threadIdx.x;
    if (k < 384) {
        float acc = 0.f;
        for (int j = 0; j < OUTD; j++) acc += Wa2[j] * Wa[j * 384 + k];
        g_weff[k] = acc;
    } else if (k == 384) {
        float acc = ba2[0];
        for (int j = 0; j < OUTD; j++) acc += Wa2[j] * ba[j];
        g_weff[384] = acc;
    }
}

// ---------------- renorm + per-row dots ----------------
__device__ __forceinline__ float warp_sum(float v) {
    #pragma unroll
    for (int off = 16; off >= 1; off >>= 1) v += __shfl_xor_sync(0xffffffffu, v, off);
    return v;
}

__global__ void krn_ent(const float* __restrict__ ent) {
    int w    = ((int)blockIdx.x * blockDim.x + threadIdx.x) >> 5;
    int lane = threadIdx.x & 31;
    if (w >= NE) return;
    float4 v = *(const float4*)&ent[(long)w * IND + lane * 4];
    float ss = warp_sum(v.x * v.x + v.y * v.y + v.z * v.z + v.w * v.w);
    float sc = fminf(1.f, 1.f / fmaxf(sqrtf(ss), 1e-12f));
    float4 r = make_float4(v.x * sc, v.y * sc, v.z * sc, v.w * sc);
    *(float4*)&g_ent_rn[(long)w * IND + lane * 4] = r;
    float4 w1 = *(const float4*)&g_weff[lane * 4];
    float4 w3 = *(const float4*)&g_weff[256 + lane * 4];
    float a1 = warp_sum(r.x * w1.x + r.y * w1.y + r.z * w1.z + r.w * w1.w);
    float a3 = warp_sum(r.x * w3.x + r.y * w3.y + r.z * w3.z + r.w * w3.w);
    if (lane == 0) { g_d1[w] = a1; g_d3[w] = a3; }
}

__global__ void krn_rel(const float* __restrict__ rel) {
    int w    = ((int)blockIdx.x * blockDim.x + threadIdx.x) >> 5;
    int lane = threadIdx.x & 31;
    if (w >= NR) return;
    float4 v = *(const float4*)&rel[(long)w * IND + lane * 4];
    float ss = warp_sum(v.x * v.x + v.y * v.y + v.z * v.z + v.w * v.w);
    float sc = fminf(1.f, 1.f / fmaxf(sqrtf(ss), 1e-12f));
    float4 r = make_float4(v.x * sc, v.y * sc, v.z * sc, v.w * sc);
    *(float4*)&g_rel_rn[(long)w * IND + lane * 4] = r;
    float4 w2 = *(const float4*)&g_weff[128 + lane * 4];
    float a2 = warp_sum(r.x * w2.x + r.y * w2.y + r.z * w2.z + r.w * w2.w);
    if (lane == 0) g_d2[w] = a2;
}

// ---------------- transpose Wa -> Wfull[384][200] ----------------
__global__ void kwf(const float* __restrict__ Wa) {
    int idx = (int)blockIdx.x * blockDim.x + threadIdx.x;
    if (idx >= KK * OUTD) return;
    int k = idx / OUTD, j = idx % OUTD;
    g_Wfull[idx] = Wa[(long)j * KK + k];
}

// ---------------- per-edge: e_b + histograms ----------------
__global__ void kedge(const int* __restrict__ trip) {
    int e = (int)blockIdx.x * blockDim.x + threadIdx.x;
    if (e >= EE) return;
    int s = trip[3 * e], r = trip[3 * e + 1], o = trip[3 * e + 2];
    float x  = g_d1[s] + g_d2[r] + g_d3[o] + g_weff[384];
    float lr = x >= 0.f ? x : 0.01f * x;
    float eb = expf(-lr);
    g_eb[e] = eb;
    atomicAdd(&g_histS[s], 1);
    atomicAdd(&g_histR[r], 1);
}

// ---------------- scan of histS (2-level) ----------------
__global__ void scanA() {
    __shared__ int sh[1024];
    int b = blockIdx.x, t = threadIdx.x;
    int i = b * 1024 + t;
    int v = (i < NE) ? g_histS[i] : 0;
    int x = v;
    sh[t] = x; __syncthreads();
    #pragma unroll
    for (int off = 1; off < 1024; off <<= 1) {
        int y = (t >= off) ? sh[t - off] : 0;
        __syncthreads();
        x += y; sh[t] = x;
        __syncthreads();
    }
    if (i < NE) g_offS[i] = x - v;
    if (t == 1023) g_bsum[b] = x;
}
__global__ void scanB() {
    if (threadIdx.x == 0 && blockIdx.x == 0) {
        int acc = 0;
        for (int b = 0; b < 98; b++) { g_boff[b] = acc; acc += g_bsum[b]; }
    }
}
__global__ void scanC() {
    int i = (int)blockIdx.x * blockDim.x + threadIdx.x;
    if (i < NE) {
        int o = g_offS[i] + g_boff[blockIdx.x * blockDim.x / 1024 + threadIdx.x / 1024];
        // note: blockDim.x == 1024, so block b handles i in [b*1024, ...)
        o = g_offS[i] + g_boff[blockIdx.x];
        g_offS[i] = o;
        g_curS[i] = o;
    }
}
__global__ void kscanR() {
    if (threadIdx.x == 0 && blockIdx.x == 0) {
        int acc = 0;
        for (int r = 0; r < NR; r++) { g_offR[r] = acc; g_curR[r] = acc; acc += g_histR[r]; }
    }
}

// ---------------- scatter edges by s and by r ----------------
__global__ void kscatter(const int* __restrict__ trip) {
    int e = (int)blockIdx.x * blockDim.x + threadIdx.x;
    if (e >= EE) return;
    int s = trip[3 * e], r = trip[3 * e + 1], o = trip[3 * e + 2];
    float eb = g_eb[e];
    int ps = atomicAdd(&g_curS[s], 1);
    g_sRO[ps] = ((unsigned int)r << 17) | (unsigned int)o;
    g_sEb[ps] = eb;
    int pr = atomicAdd(&g_curR[r], 1);
    g_rS[pr] = s; g_rO[pr] = o; g_rE[pr] = eb;
}

// ---------------- warp-per-node: P2, P3, inv (no atomics) ----------------
__global__ void knode() {
    int w    = ((int)blockIdx.x * blockDim.x + threadIdx.x) >> 5;
    int lane = threadIdx.x & 31;
    if (w >= NE) return;
    int beg = g_offS[w], deg = g_histS[w];
    float4 a2 = make_float4(0.f, 0.f, 0.f, 0.f);
    float4 a3 = a2;
    float ebs = 0.f;
    for (int i = beg; i < beg + deg; i++) {
        unsigned int ro = g_sRO[i];
        float e = g_sEb[i];
        int r = ro >> 17;
        int o = ro & 0x1FFFF;
        float4 rv = *(const float4*)&g_rel_rn[(long)r * IND + lane * 4];
        float4 ov = *(const float4*)&g_ent_rn[(long)o * IND + lane * 4];
        a2.x += e * rv.x; a2.y += e * rv.y; a2.z += e * rv.z; a2.w += e * rv.w;
        a3.x += e * ov.x; a3.y += e * ov.y; a3.z += e * ov.z; a3.w += e * ov.w;
        ebs += e;
    }
    float inv = (ebs > 0.f) ? 1.f / ebs : 0.f;
    a2.x *= inv; a2.y *= inv; a2.z *= inv; a2.w *= inv;
    a3.x *= inv; a3.y *= inv; a3.z *= inv; a3.w *= inv;
    *(float4*)&g_P2[(long)w * IND + lane * 4] = a2;
    *(float4*)&g_P3[(long)w * IND + lane * 4] = a3;
    if (lane == 0) g_inv[w] = inv;
}

// ---------------- relation sums: block per (relation, chunk) ----------------
__global__ void kr() {
    int r = blockIdx.x;
    int chunk = blockIdx.y;     // 0..7
    int t = threadIdx.x;
    int d = t & 127;
    bool lo = t < 128;
    int base = g_offR[r], cnt = g_histR[r];
    int c0 = base + (int)((long)chunk * cnt / 8);
    int c1 = base + (int)((long)(chunk + 1) * cnt / 8);
    if (c1 <= c0) return;
    float acc = 0.f, ebsum = 0.f;
    #pragma unroll 4
    for (int i = c0; i < c1; i++) {
        float e = g_rE[i];
        int node = lo ? g_rS[i] : g_rO[i];
        acc += e * g_ent_rn[(long)node * IND + d];
        ebsum += e;
    }
    atomicAdd(lo ? &g_S1[r * IND + d] : &g_S2[r * IND + d], acc);
    if (t == 0) atomicAdd(&g_ebr[r], ebsum);
}

// ---------------- main GEMM: FFMA2, BM=128 BN=64, microtile 8x4 ----------------
#define BM 128
#define BN 64
#define KT 16
__global__ void __launch_bounds__(256) kg(const float* __restrict__ ba,
                                          float* __restrict__ out) {
    __shared__ __align__(16) float Xs[KT][BM + 4];
    __shared__ __align__(16) float Ws[KT][BN];
    int n0 = (int)blockIdx.x * BM;
    int j0 = (int)blockIdx.y * BN;
    int tid = threadIdx.x;
    int tx = tid & 15, ty = tid >> 4;
    unsigned long long acc[8][2];
    #pragma unroll
    for (int i = 0; i < 8; i++) { acc[i][0] = 0ULL; acc[i][1] = 0ULL; }

    int xi = tid >> 1;               // row 0..127
    int xh = (tid & 1) * 8;          // k sub-offset 0 or 8
    int nrow = n0 + xi;
    bool nok = nrow < NE;
    int wk = tid >> 4;               // W tile row 0..15
    int wj = (tid & 15) * 4;

    for (int c = 0; c < KK / KT; c++) {
        int k0 = c * KT;
        const float* src = (c < 8) ? g_ent_rn : (c < 16) ? g_P2 : g_P3;
        int koff = k0 & 127;
        float4 v0 = make_float4(0.f, 0.f, 0.f, 0.f), v1 = v0;
        if (nok) {
            const float4* p = (const float4*)&src[(long)nrow * IND + koff + xh];
            v0 = p[0]; v1 = p[1];
        }
        float4 wv = *(const float4*)&g_Wfull[(long)(k0 + wk) * OUTD + j0 + wj];
        __syncthreads();
        Xs[xh + 0][xi] = v0.x; Xs[xh + 1][xi] = v0.y;
        Xs[xh + 2][xi] = v0.z; Xs[xh + 3][xi] = v0.w;
        Xs[xh + 4][xi] = v1.x; Xs[xh + 5][xi] = v1.y;
        Xs[xh + 6][xi] = v1.z; Xs[xh + 7][xi] = v1.w;
        *(float4*)&Ws[wk][wj] = wv;
        __syncthreads();
        #pragma unroll
        for (int kk = 0; kk < KT; kk++) {
            float4 a0 = *(float4*)&Xs[kk][ty * 8];
            float4 a1 = *(float4*)&Xs[kk][ty * 8 + 4];
            ulonglong2 b = *(ulonglong2*)&Ws[kk][tx * 4];
            float av[8] = {a0.x, a0.y, a0.z, a0.w, a1.x, a1.y, a1.z, a1.w};
            #pragma unroll
            for (int ii = 0; ii < 8; ii++) {
                unsigned long long ad = dup2(av[ii]);
                fma2(acc[ii][0], ad, b.x);
                fma2(acc[ii][1], ad, b.y);
            }
        }
    }
    float4 bav = *(const float4*)&ba[j0 + tx * 4];
    #pragma unroll
    for (int ii = 0; ii < 8; ii++) {
        int n = n0 + ty * 8 + ii;
        if (n >= NE) continue;
        float inv = g_inv[n];
        float l0, h0, l1, h1;
        unpack2(acc[ii][0], l0, h0);
        unpack2(acc[ii][1], l1, h1);
        float4 o;
        if (inv > 0.f) {
            o.x = fmaxf(l0 + bav.x, 0.f);
            o.y = fmaxf(h0 + bav.y, 0.f);
            o.z = fmaxf(l1 + bav.z, 0.f);
            o.w = fmaxf(h1 + bav.w, 0.f);
        } else {
            o = make_float4(0.f, 0.f, 0.f, 0.f);
        }
        *(float4*)&out[(long)n * OUTD + j0 + tx * 4] = o;
    }
}

// ---------------- tail GEMM: columns 192..199 ----------------
__global__ void __launch_bounds__(256) kgt(const float* __restrict__ ba,
                                           float* __restrict__ out) {
    __shared__ __align__(16) float Xs[KT][BM + 4];
    __shared__ float Ws[KT][8];
    int n0 = (int)blockIdx.x * BM;
    int tid = threadIdx.x;
    int tx = tid & 7, ty = tid >> 3;     // ty 0..31, 4 rows each
    float acc[4] = {0.f, 0.f, 0.f, 0.f};
    int xi = tid >> 1;
    int xh = (tid & 1) * 8;
    int nrow = n0 + xi;
    bool nok = nrow < NE;
    for (int c = 0; c < KK / KT; c++) {
        int k0 = c * KT;
        const float* src = (c < 8) ? g_ent_rn : (c < 16) ? g_P2 : g_P3;
        int koff = k0 & 127;
        float4 v0 = make_float4(0.f, 0.f, 0.f, 0.f), v1 = v0;
        if (nok) {
            const float4* p = (const float4*)&src[(long)nrow * IND + koff + xh];
            v0 = p[0]; v1 = p[1];
        }
        float wv = 0.f;
        if (tid < KT * 8) wv = g_Wfull[(long)(k0 + (tid >> 3)) * OUTD + 192 + (tid & 7)];
        __syncthreads();
        Xs[xh + 0][xi] = v0.x; Xs[xh + 1][xi] = v0.y;
        Xs[xh + 2][xi] = v0.z; Xs[xh + 3][xi] = v0.w;
        Xs[xh + 4][xi] = v1.x; Xs[xh + 5][xi] = v1.y;
        Xs[xh + 6][xi] = v1.z; Xs[xh + 7][xi] = v1.w;
        if (tid < KT * 8) Ws[tid >> 3][tid & 7] = wv;
        __syncthreads();
        #pragma unroll
        for (int kk = 0; kk < KT; kk++) {
            float b = Ws[kk][tx];
            float4 a = *(float4*)&Xs[kk][ty * 4];
            acc[0] += a.x * b; acc[1] += a.y * b;
            acc[2] += a.z * b; acc[3] += a.w * b;
        }
        __syncthreads();
    }
    float bb = ba[192 + tx];
    #pragma unroll
    for (int ii = 0; ii < 4; ii++) {
        int n = n0 + ty * 4 + ii;
        if (n >= NE) continue;
        float inv = g_inv[n];
        out[(long)n * OUTD + 192 + tx] = (inv > 0.f) ? fmaxf(acc[ii] + bb, 0.f) : 0.f;
    }
}

// ---------------- h_rel ----------------
__global__ void kh(const float* __restrict__ ba, float* __restrict__ out) {
    __shared__ float s1[IND], s2[IND], rr[IND];
    int r = blockIdx.x, j = threadIdx.x;   // 200 threads
    if (j < IND) {
        s1[j] = g_S1[r * IND + j];
        s2[j] = g_S2[r * IND + j];
        rr[j] = g_rel_rn[r * IND + j];
    }
    __syncthreads();
    float ebr  = g_ebr[r];
    float icnt = 1.f / fmaxf((float)g_histR[r], 1.f);
    float acc = ebr * ba[j];
    #pragma unroll 4
    for (int c = 0; c < IND; c++) {
        acc += s1[c] * g_Wfull[c * OUTD + j];
        acc += (ebr * rr[c]) * g_Wfull[(IND + c) * OUTD + j];
        acc += s2[c] * g_Wfull[(2 * IND + c) * OUTD + j];
    }
    out[(long)NE * OUTD + r * OUTD + j] = fmaxf(acc * icnt, 0.f);
}

// ---------------- launch ----------------
extern "C" void kernel_launch(void* const* d_in, const int* in_sizes, int n_in,
                              void* d_out, int out_size) {
    const int*   trip = (const int*)d_in[0];
    const float* ent  = (const float*)d_in[1];
    const float* rel  = (const float*)d_in[2];
    const float* Wa   = (const float*)d_in[3];
    const float* ba   = (const float*)d_in[4];
    const float* Wa2  = (const float*)d_in[5];
    const float* ba2  = (const float*)d_in[6];
    float* out = (float*)d_out;

    kz<<<(NE + 255) / 256, 256>>>();
    kw<<<1, 512>>>(Wa, ba, Wa2, ba2);
    krn_rel<<<(NR * 32 + 255) / 256, 256>>>(rel);
    krn_ent<<<(NE * 32 + 255) / 256, 256>>>(ent);
    kwf<<<(KK * OUTD + 255) / 256, 256>>>(Wa);
    kedge<<<(EE + 255) / 256, 256>>>(trip);
    scanA<<<98, 1024>>>();
    scanB<<<1, 1>>>();
    scanC<<<98, 1024>>>();
    kscanR<<<1, 1>>>();
    kscatter<<<(EE + 255) / 256, 256>>>(trip);
    knode<<<(NE * 32 + 255) / 256, 256>>>();
    kr<<<dim3(NR, 8), 256>>>();
    dim3 gg((NE + BM - 1) / BM, 3);
    kg<<<gg, 256>>>(ba, out);
    kgt<<<(NE + BM - 1) / BM, 256>>>(ba, out);
    kh<<<NR, OUTD>>>(ba, out);
}

// round 6
// speedup vs baseline: 3.7000x; 1.4617x over previous
#include <cuda_runtime.h>
#include <math.h>
#include <stdint.h>

#define NE   100000
#define NR   200
#define EE   500000
#define IND  128
#define OUTD 200
#define KK   384      // 128 ent_s | 128 P2(rel) | 128 P3(obj)
#define JP   208      // padded output cols

// ---------------- scratch ----------------
__device__ float g_ent_rn[NE * IND];
__device__ float g_rel_rn[NR * IND];
__device__ float g_P2[NE * IND];
__device__ float g_P3[NE * IND];
__device__ float g_inv[NE];
__device__ float g_d1[NE];
__device__ float g_d3[NE];
__device__ float g_d2[NR];
__device__ float g_weff[385];
__device__ float g_Wfull[KK * JP];        // [k][j], tf32-rounded, zero-padded j>=200
__device__ float g_eb[EE];
__device__ int   g_histS[NE];
__device__ int   g_offS[NE];
__device__ int   g_curS[NE];
__device__ int   g_histR[NR];
__device__ int   g_offR[NR];
__device__ int   g_curR[NR];
__device__ int   g_bsum[128];
__device__ int   g_boff[128];
__device__ unsigned int g_sRO[EE];
__device__ float g_sEb[EE];
__device__ int   g_rS[EE];
__device__ int   g_rO[EE];
__device__ float g_rE[EE];
__device__ float g_S1[NR * IND];
__device__ float g_S2[NR * IND];
__device__ float g_ebr[NR];

// ---------------- helpers ----------------
__device__ __forceinline__ uint32_t smem_u32(const void* p) {
    uint32_t a;
    asm("{ .reg .u64 t; cvta.to.shared.u64 t, %1; cvt.u32.u64 %0, t; }"
        : "=r"(a) : "l"(p));
    return a;
}
__device__ __forceinline__ float to_tf32(float x) {
    uint32_t u;
    asm("cvt.rna.tf32.f32 %0, %1;" : "=r"(u) : "f"(x));
    return __uint_as_float(u);
}
__device__ __forceinline__ void mma_tf32(float* c, const uint32_t* a, const uint32_t* b) {
    asm volatile(
        "mma.sync.aligned.m16n8k8.row.col.f32.tf32.tf32.f32 "
        "{%0,%1,%2,%3}, {%4,%5,%6,%7}, {%8,%9}, {%0,%1,%2,%3};"
        : "+f"(c[0]), "+f"(c[1]), "+f"(c[2]), "+f"(c[3])
        : "r"(a[0]), "r"(a[1]), "r"(a[2]), "r"(a[3]), "r"(b[0]), "r"(b[1]));
}
__device__ __forceinline__ float warp_sum(float v) {
    #pragma unroll
    for (int off = 16; off >= 1; off >>= 1) v += __shfl_xor_sync(0xffffffffu, v, off);
    return v;
}

// ---------------- zero small scratch ----------------
__global__ void kz() {
    int i = (int)blockIdx.x * blockDim.x + threadIdx.x;
    if (i < NE) g_histS[i] = 0;
    if (i < NR) { g_histR[i] = 0; g_ebr[i] = 0.f; }
    if (i < NR * IND) { g_S1[i] = 0.f; g_S2[i] = 0.f; }
}

// ---------------- w_eff = Wa2 @ Wa ; bias_eff ----------------
__global__ void kw(const float* __restrict__ Wa, const float* __restrict__ ba,
                   const float* __restrict__ Wa2, const float* __restrict__ ba2) {
    int k = threadIdx.x;
    if (k < 384) {
        float acc = 0.f;
        for (int j = 0; j < OUTD; j++) acc += Wa2[j] * Wa[j * 384 + k];
        g_weff[k] = acc;
    } else if (k == 384) {
        float acc = ba2[0];
        for (int j = 0; j < OUTD; j++) acc += Wa2[j] * ba[j];
        g_weff[384] = acc;
    }
}

// ---------------- renorm + per-row dots (tf32-rounded stores) ----------------
__global__ void krn_ent(const float* __restrict__ ent) {
    int w    = ((int)blockIdx.x * blockDim.x + threadIdx.x) >> 5;
    int lane = threadIdx.x & 31;
    if (w >= NE) return;
    float4 v = *(const float4*)&ent[(long)w * IND + lane * 4];
    float ss = warp_sum(v.x * v.x + v.y * v.y + v.z * v.z + v.w * v.w);
    float sc = fminf(1.f, 1.f / fmaxf(sqrtf(ss), 1e-12f));
    float4 r = make_float4(to_tf32(v.x * sc), to_tf32(v.y * sc),
                           to_tf32(v.z * sc), to_tf32(v.w * sc));
    *(float4*)&g_ent_rn[(long)w * IND + lane * 4] = r;
    float4 w1 = *(const float4*)&g_weff[lane * 4];
    float4 w3 = *(const float4*)&g_weff[256 + lane * 4];
    float a1 = warp_sum(r.x * w1.x + r.y * w1.y + r.z * w1.z + r.w * w1.w);
    float a3 = warp_sum(r.x * w3.x + r.y * w3.y + r.z * w3.z + r.w * w3.w);
    if (lane == 0) { g_d1[w] = a1; g_d3[w] = a3; }
}

__global__ void krn_rel(const float* __restrict__ rel) {
    int w    = ((int)blockIdx.x * blockDim.x + threadIdx.x) >> 5;
    int lane = threadIdx.x & 31;
    if (w >= NR) return;
    float4 v = *(const float4*)&rel[(long)w * IND + lane * 4];
    float ss = warp_sum(v.x * v.x + v.y * v.y + v.z * v.z + v.w * v.w);
    float sc = fminf(1.f, 1.f / fmaxf(sqrtf(ss), 1e-12f));
    float4 r = make_float4(to_tf32(v.x * sc), to_tf32(v.y * sc),
                           to_tf32(v.z * sc), to_tf32(v.w * sc));
    *(float4*)&g_rel_rn[(long)w * IND + lane * 4] = r;
    float4 w2 = *(const float4*)&g_weff[128 + lane * 4];
    float a2 = warp_sum(r.x * w2.x + r.y * w2.y + r.z * w2.z + r.w * w2.w);
    if (lane == 0) g_d2[w] = a2;
}

// ---------------- Wfull[384][208] = Wa^T, tf32-rounded, zero pad ----------------
__global__ void kwf(const float* __restrict__ Wa) {
    int idx = (int)blockIdx.x * blockDim.x + threadIdx.x;
    if (idx >= KK * JP) return;
    int k = idx / JP, j = idx % JP;
    g_Wfull[idx] = (j < OUTD) ? to_tf32(Wa[(long)j * KK + k]) : 0.f;
}

// ---------------- per-edge: e_b + histograms ----------------
__global__ void kedge(const int* __restrict__ trip) {
    int e = (int)blockIdx.x * blockDim.x + threadIdx.x;
    if (e >= EE) return;
    int s = trip[3 * e], r = trip[3 * e + 1], o = trip[3 * e + 2];
    float x  = g_d1[s] + g_d2[r] + g_d3[o] + g_weff[384];
    float lr = x >= 0.f ? x : 0.01f * x;
    float eb = expf(-lr);
    g_eb[e] = eb;
    atomicAdd(&g_histS[s], 1);
    atomicAdd(&g_histR[r], 1);
}

// ---------------- scan of histS (2-level) ----------------
__global__ void scanA() {
    __shared__ int sh[1024];
    int b = blockIdx.x, t = threadIdx.x;
    int i = b * 1024 + t;
    int v = (i < NE) ? g_histS[i] : 0;
    int x = v;
    sh[t] = x; __syncthreads();
    #pragma unroll
    for (int off = 1; off < 1024; off <<= 1) {
        int y = (t >= off) ? sh[t - off] : 0;
        __syncthreads();
        x += y; sh[t] = x;
        __syncthreads();
    }
    if (i < NE) g_offS[i] = x - v;
    if (t == 1023) g_bsum[b] = x;
}
__global__ void scanB() {
    if (threadIdx.x == 0 && blockIdx.x == 0) {
        int acc = 0;
        for (int b = 0; b < 98; b++) { g_boff[b] = acc; acc += g_bsum[b]; }
    }
}
__global__ void scanC() {
    int i = (int)blockIdx.x * blockDim.x + threadIdx.x;
    if (i < NE) {
        int o = g_offS[i] + g_boff[blockIdx.x];
        g_offS[i] = o;
        g_curS[i] = o;
    }
}
__global__ void kscanR() {
    if (threadIdx.x == 0 && blockIdx.x == 0) {
        int acc = 0;
        for (int r = 0; r < NR; r++) { g_offR[r] = acc; g_curR[r] = acc; acc += g_histR[r]; }
    }
}

// ---------------- scatter edges by s and by r ----------------
__global__ void kscatter(const int* __restrict__ trip) {
    int e = (int)blockIdx.x * blockDim.x + threadIdx.x;
    if (e >= EE) return;
    int s = trip[3 * e], r = trip[3 * e + 1], o = trip[3 * e + 2];
    float eb = g_eb[e];
    int ps = atomicAdd(&g_curS[s], 1);
    g_sRO[ps] = ((unsigned int)r << 17) | (unsigned int)o;
    g_sEb[ps] = eb;
    int pr = atomicAdd(&g_curR[r], 1);
    g_rS[pr] = s; g_rO[pr] = o; g_rE[pr] = eb;
}

// ---------------- warp-per-node: P2, P3, inv (tf32-rounded) ----------------
__global__ void knode() {
    int w    = ((int)blockIdx.x * blockDim.x + threadIdx.x) >> 5;
    int lane = threadIdx.x & 31;
    if (w >= NE) return;
    int beg = g_offS[w], deg = g_histS[w];
    float4 a2 = make_float4(0.f, 0.f, 0.f, 0.f);
    float4 a3 = a2;
    float ebs = 0.f;
    for (int i = beg; i < beg + deg; i++) {
        unsigned int ro = g_sRO[i];
        float e = g_sEb[i];
        int r = ro >> 17;
        int o = ro & 0x1FFFF;
        float4 rv = *(const float4*)&g_rel_rn[(long)r * IND + lane * 4];
        float4 ov = *(const float4*)&g_ent_rn[(long)o * IND + lane * 4];
        a2.x += e * rv.x; a2.y += e * rv.y; a2.z += e * rv.z; a2.w += e * rv.w;
        a3.x += e * ov.x; a3.y += e * ov.y; a3.z += e * ov.z; a3.w += e * ov.w;
        ebs += e;
    }
    float inv = (ebs > 0.f) ? 1.f / ebs : 0.f;
    float4 o2 = make_float4(to_tf32(a2.x * inv), to_tf32(a2.y * inv),
                            to_tf32(a2.z * inv), to_tf32(a2.w * inv));
    float4 o3 = make_float4(to_tf32(a3.x * inv), to_tf32(a3.y * inv),
                            to_tf32(a3.z * inv), to_tf32(a3.w * inv));
    *(float4*)&g_P2[(long)w * IND + lane * 4] = o2;
    *(float4*)&g_P3[(long)w * IND + lane * 4] = o3;
    if (lane == 0) g_inv[w] = inv;
}

// ---------------- relation sums ----------------
__global__ void kr() {
    int r = blockIdx.x;
    int chunk = blockIdx.y;
    int t = threadIdx.x;
    int d = t & 127;
    bool lo = t < 128;
    int base = g_offR[r], cnt = g_histR[r];
    int c0 = base + (int)((long)chunk * cnt / 8);
    int c1 = base + (int)((long)(chunk + 1) * cnt / 8);
    if (c1 <= c0) return;
    float acc = 0.f, ebsum = 0.f;
    #pragma unroll 4
    for (int i = c0; i < c1; i++) {
        float e = g_rE[i];
        int node = lo ? g_rS[i] : g_rO[i];
        acc += e * g_ent_rn[(long)node * IND + d];
        ebsum += e;
    }
    atomicAdd(lo ? &g_S1[r * IND + d] : &g_S2[r * IND + d], acc);
    if (t == 0) atomicAdd(&g_ebr[r], ebsum);
}

// ================= main GEMM via mma.sync tf32 =================
// out[n][j] = relu(X[n]@Wa[j] + ba[j]) masked by inv>0 ; X = [ent_rn|P2|P3]
// grid (2, 782): x = column half (104 cols), y = 128-row tile (x fastest -> L2 reuse of X)
#define BM   128
#define BNH  104
#define APAD 36
#define A_BUF_BYTES (BM * APAD * 4)     // 18432
#define B_BUF_BYTES (32 * BNH * 4)      // 13312
#define SOFF_A    1024
#define SOFF_B    (SOFF_A + 2 * A_BUF_BYTES)
#define SMEM_MMA  (SOFF_B + 2 * B_BUF_BYTES)   // 64512 B

__global__ void __launch_bounds__(256) kmma(const float* __restrict__ ba,
                                            float* __restrict__ out) {
    extern __shared__ __align__(128) char sm[];
    uint32_t sb = smem_u32(sm);
    float* bias = (float*)sm;               // 208 floats
    int tid = threadIdx.x, wid = tid >> 5, lane = tid & 31;
    int n0 = (int)blockIdx.y * BM;
    int j0 = (int)blockIdx.x * BNH;
    if (tid < JP) bias[tid] = (tid < OUTD) ? ba[tid] : 0.f;

    // ---- async chunk loader ----
    auto issue = [&](int c, int buf) {
        const float* srcX = (c < 4) ? g_ent_rn : (c < 8) ? g_P2 : g_P3;
        int koff = (c & 3) * 32;
        uint32_t abase = sb + SOFF_A + buf * A_BUF_BYTES;
        #pragma unroll
        for (int it = 0; it < 4; it++) {
            int idx = tid + it * 256;            // 0..1023
            int row = idx >> 3, kq = idx & 7;
            int n = n0 + row;
            int nc = (n < NE) ? n : (NE - 1);
            uint32_t dst = abase + (uint32_t)(row * (APAD * 4) + kq * 16);
            const float* src = srcX + (size_t)nc * IND + koff + kq * 4;
            uint32_t sz = (n < NE) ? 16u : 0u;
            asm volatile("cp.async.ca.shared.global [%0], [%1], 16, %2;"
                         :: "r"(dst), "l"(src), "r"(sz));
        }
        uint32_t bbase = sb + SOFF_B + buf * B_BUF_BYTES;
        #pragma unroll
        for (int it = 0; it < 4; it++) {
            int idx = tid + it * 256;            // need 832 = 32k x 26 f4
            if (idx < 832) {
                int k = idx & 31, c4 = idx >> 5;
                uint32_t dst = bbase + (uint32_t)(k * (BNH * 4) + c4 * 16);
                const float* src = g_Wfull + (size_t)(c * 32 + k) * JP + j0 + c4 * 4;
                asm volatile("cp.async.ca.shared.global [%0], [%1], 16;"
                             :: "r"(dst), "l"(src));
            }
        }
        asm volatile("cp.async.commit_group;");
    };

    float acc[13][4];
    #pragma unroll
    for (int t = 0; t < 13; t++)
        #pragma unroll
        for (int q = 0; q < 4; q++) acc[t][q] = 0.f;

    issue(0, 0);

    int r0   = wid * 16 + (lane >> 2);
    int kk   = lane & 3;
    int col0 = lane >> 2;

    for (int c = 0; c < 12; c++) {
        if (c < 11) issue(c + 1, (c + 1) & 1);
        if (c < 11) asm volatile("cp.async.wait_group 1;");
        else        asm volatile("cp.async.wait_group 0;");
        __syncthreads();
        const uint32_t* A32 = (const uint32_t*)(sm + SOFF_A + (c & 1) * A_BUF_BYTES);
        const uint32_t* B32 = (const uint32_t*)(sm + SOFF_B + (c & 1) * B_BUF_BYTES);
        #pragma unroll
        for (int s = 0; s < 4; s++) {
            uint32_t a[4];
            a[0] = A32[r0 * APAD + s * 8 + kk];
            a[1] = A32[(r0 + 8) * APAD + s * 8 + kk];
            a[2] = A32[r0 * APAD + s * 8 + kk + 4];
            a[3] = A32[(r0 + 8) * APAD + s * 8 + kk + 4];
            #pragma unroll
            for (int t = 0; t < 13; t++) {
                uint32_t b[2];
                b[0] = B32[(s * 8 + kk) * BNH + t * 8 + col0];
                b[1] = B32[(s * 8 + kk + 4) * BNH + t * 8 + col0];
                mma_tf32(acc[t], a, b);
            }
        }
        __syncthreads();
    }

    // ---- epilogue ----
    int n_a = n0 + r0, n_b = n0 + r0 + 8;
    float inva = (n_a < NE) ? g_inv[n_a] : 0.f;
    float invb = (n_b < NE) ? g_inv[n_b] : 0.f;
    #pragma unroll
    for (int t = 0; t < 13; t++) {
        int j = j0 + t * 8 + 2 * (lane & 3);
        if (j >= OUTD) continue;
        float bj0 = bias[j], bj1 = bias[j + 1];
        if (n_a < NE) {
            float2 v;
            v.x = (inva > 0.f) ? fmaxf(acc[t][0] + bj0, 0.f) : 0.f;
            v.y = (inva > 0.f) ? fmaxf(acc[t][1] + bj1, 0.f) : 0.f;
            *(float2*)&out[(size_t)n_a * OUTD + j] = v;
        }
        if (n_b < NE) {
            float2 v;
            v.x = (invb > 0.f) ? fmaxf(acc[t][2] + bj0, 0.f) : 0.f;
            v.y = (invb > 0.f) ? fmaxf(acc[t][3] + bj1, 0.f) : 0.f;
            *(float2*)&out[(size_t)n_b * OUTD + j] = v;
        }
    }
}

// ---------------- h_rel ----------------
__global__ void kh(const float* __restrict__ ba, float* __restrict__ out) {
    __shared__ float s1[IND], s2[IND], rr[IND];
    int r = blockIdx.x, j = threadIdx.x;   // 200 threads
    if (j < IND) {
        s1[j] = g_S1[r * IND + j];
        s2[j] = g_S2[r * IND + j];
        rr[j] = g_rel_rn[r * IND + j];
    }
    __syncthreads();
    float ebr  = g_ebr[r];
    float icnt = 1.f / fmaxf((float)g_histR[r], 1.f);
    float acc = ebr * ba[j];
    #pragma unroll 4
    for (int c = 0; c < IND; c++) {
        acc += s1[c] * g_Wfull[c * JP + j];
        acc += (ebr * rr[c]) * g_Wfull[(IND + c) * JP + j];
        acc += s2[c] * g_Wfull[(2 * IND + c) * JP + j];
    }
    out[(long)NE * OUTD + r * OUTD + j] = fmaxf(acc * icnt, 0.f);
}

// ---------------- launch ----------------
extern "C" void kernel_launch(void* const* d_in, const int* in_sizes, int n_in,
                              void* d_out, int out_size) {
    const int*   trip = (const int*)d_in[0];
    const float* ent  = (const float*)d_in[1];
    const float* rel  = (const float*)d_in[2];
    const float* Wa   = (const float*)d_in[3];
    const float* ba   = (const float*)d_in[4];
    const float* Wa2  = (const float*)d_in[5];
    const float* ba2  = (const float*)d_in[6];
    float* out = (float*)d_out;

    cudaFuncSetAttribute(kmma, cudaFuncAttributeMaxDynamicSharedMemorySize, SMEM_MMA);

    kz<<<(NE + 255) / 256, 256>>>();
    kw<<<1, 512>>>(Wa, ba, Wa2, ba2);
    krn_rel<<<(NR * 32 + 255) / 256, 256>>>(rel);
    krn_ent<<<(NE * 32 + 255) / 256, 256>>>(ent);
    kwf<<<(KK * JP + 255) / 256, 256>>>(Wa);
    kedge<<<(EE + 255) / 256, 256>>>(trip);
    scanA<<<98, 1024>>>();
    scanB<<<1, 1>>>();
    scanC<<<98, 1024>>>();
    kscanR<<<1, 1>>>();
    kscatter<<<(EE + 255) / 256, 256>>>(trip);
    knode<<<(NE * 32 + 255) / 256, 256>>>();
    kr<<<dim3(NR, 8), 256>>>();
    kmma<<<dim3(2, (NE + BM - 1) / BM), 256, SMEM_MMA>>>(ba, out);
    kh<<<NR, OUTD>>>(ba, out);
}